// round 16
// baseline (speedup 1.0000x reference)
#include <cuda_runtime.h>
#include <cuda_bf16.h>

// Problem constants (fixed shapes from setup_inputs)
#define BB      4
#define NPTS    8192
#define SS      2048
#define CC      64
#define NSAMPLE 32
#define R2      0.04f     // 0.2^2
#define OUTCH   (3 + CC)  // 67

#define WPB     2         // warps per block (qg)
#define TSTRIDE 132       // transpose smem row stride (floats) — mult of 4

// Scratch: transposed features [B,N,C] (8MB); xyz+p2 AoS [B,N] float4 (512KB)
__device__ float  g_featT[(size_t)BB * NPTS * CC];
__device__ float4 g_xyzP4[(size_t)BB * NPTS];

// ---------------------------------------------------------------------------
// Kernel 1: transpose features [B,C,N] -> [B,N,C], fully vectorized
// (round-13 version, validated). Last y-slice packs xyz into float4
// (x, y, z, p2), p2 in EXACT reference rounding.
// ---------------------------------------------------------------------------
__global__ __launch_bounds__(256) void transpose_kernel(
    const float* __restrict__ feat,
    const float* __restrict__ xyz)
{
    const int b = blockIdx.z;

    if (blockIdx.y == CC / 32) {
        const int t = threadIdx.y * 8 + threadIdx.x;
        if (t < 128) {
            const int n = blockIdx.x * 128 + t;
            const float x = __ldg(xyz + ((size_t)b * NPTS + n) * 3 + 0);
            const float y = __ldg(xyz + ((size_t)b * NPTS + n) * 3 + 1);
            const float z = __ldg(xyz + ((size_t)b * NPTS + n) * 3 + 2);
            const float p2 = __fadd_rn(__fadd_rn(__fmul_rn(x, x),
                                                 __fmul_rn(y, y)),
                                       __fmul_rn(z, z));
            g_xyzP4[(size_t)b * NPTS + n] = make_float4(x, y, z, p2);
        }
        return;
    }

    __shared__ float tile[32 * TSTRIDE];

    const int n0 = blockIdx.x * 128;
    const int c0 = blockIdx.y * 32;
    const int tx = threadIdx.x;            // 0..7
    const int ty = threadIdx.y;            // 0..31

    const float* fb = feat + ((size_t)b * CC + c0 + ty) * NPTS + n0;
#pragma unroll
    for (int i = 0; i < 4; i++) {
        const float4 v = __ldg((const float4*)(fb + i * 32) + tx);
        *(float4*)&tile[ty * TSTRIDE + i * 32 + 4 * tx] = v;
    }
    __syncthreads();

    float* fT = g_featT + (size_t)b * NPTS * CC;
#pragma unroll
    for (int i = 0; i < 4; i++) {
        const int n = i * 32 + ty;
        float4 o;
        o.x = tile[(4 * tx + 0) * TSTRIDE + n];
        o.y = tile[(4 * tx + 1) * TSTRIDE + n];
        o.z = tile[(4 * tx + 2) * TSTRIDE + n];
        o.w = tile[(4 * tx + 3) * TSTRIDE + n];
        *(float4*)(fT + (size_t)(n0 + n) * CC + c0 + 4 * tx) = o;
    }
}

// ---------------------------------------------------------------------------
// Kernel 2: fused ball query + group (round-14 champion + sparser break).
// One warp per query, 2 warps/block. Scan: float4 (x,y,z,p2), ping-pong
// prefetch, skip-empty chunks, break check once per 256 points (positions
// past NSAMPLE are rejected by the pos guard -> selection bit-identical).
// Gather: round-13 wavefront-optimal pattern (validated).
// ---------------------------------------------------------------------------
__global__ __launch_bounds__(64) void qg_kernel(
    const float* __restrict__ new_xyz,  // [B, S, 3]
    float* __restrict__ out)            // [B, 67, S, 32]
{
    __shared__ int   sidx[WPB][NSAMPLE];
    __shared__ float tile[WPB][NSAMPLE * 33];

    const int warp = threadIdx.x >> 5;
    const int lane = threadIdx.x & 31;
    const int w    = blockIdx.x * WPB + warp;  // query id in [0, B*S)
    const int b    = w / SS;
    const int s    = w % SS;

    const float* qptr = new_xyz + ((size_t)b * SS + s) * 3;
    const float qx = qptr[0], qy = qptr[1], qz = qptr[2];
    // Reference arithmetic EXACTLY (plain rn ops, no contraction):
    const float q2 = __fadd_rn(__fadd_rn(__fmul_rn(qx, qx), __fmul_rn(qy, qy)),
                               __fmul_rn(qz, qz));

    const float4* xp = g_xyzP4 + (size_t)b * NPTS;
    const unsigned lmask = (1u << lane) - 1u;

    int cnt = 0;

    // Evaluate one 128-point chunk held in p4[4]; update cnt/sidx.
    auto process = [&](const float4* p4, int base) {
        bool in[4];
#pragma unroll
        for (int r = 0; r < 4; r++) {
            const float4 p = p4[r];
            const float qpd = __fadd_rn(__fadd_rn(__fmul_rn(qx, p.x),
                                                  __fmul_rn(qy, p.y)),
                                        __fmul_rn(qz, p.z));
            const float d2  = __fadd_rn(__fadd_rn(q2, p.w),
                                        __fmul_rn(-2.0f, qpd));
            in[r] = d2 < R2;
        }
        unsigned m[4];
#pragma unroll
        for (int r = 0; r < 4; r++) m[r] = __ballot_sync(0xffffffffu, in[r]);

        // Skip all bookkeeping when the chunk has no hits (common on tails)
        if ((m[0] | m[1] | m[2] | m[3]) != 0u) {
            int pre[4];
            pre[0] = cnt;
            pre[1] = pre[0] + __popc(m[0]);
            pre[2] = pre[1] + __popc(m[1]);
            pre[3] = pre[2] + __popc(m[2]);
            const int newcnt = pre[3] + __popc(m[3]);
#pragma unroll
            for (int r = 0; r < 4; r++) {
                if (in[r]) {
                    const int pos = pre[r] + __popc(m[r] & lmask);
                    if (pos < NSAMPLE) sidx[warp][pos] = base + 32 * r + lane;
                }
            }
            cnt = newcnt;
        }
    };

    // Ping-pong scan: process A while prefetching B and vice versa.
    // Break decision once per 256 points (overshoot writes are pos-guarded).
    {
        float4 A[4], B[4];
#pragma unroll
        for (int r = 0; r < 4; r++) A[r] = __ldg(xp + 32 * r + lane);

        int base = 0;
        for (;;) {
            if (base + 128 < NPTS) {
#pragma unroll
                for (int r = 0; r < 4; r++)
                    B[r] = __ldg(xp + base + 128 + 32 * r + lane);
            }
            process(A, base);
            base += 128;
            if (base >= NPTS) break;

            if (base + 128 < NPTS) {
#pragma unroll
                for (int r = 0; r < 4; r++)
                    A[r] = __ldg(xp + base + 128 + 32 * r + lane);
            }
            process(B, base);
            base += 128;
            if (cnt >= NSAMPLE || base >= NPTS) break;
        }
    }

    // Empty-ball fallback: slot 0 = point 0 (matches reference idx=0)
    if (cnt == 0 && lane == 0) sidx[warp][0] = 0;
    __syncwarp();

    const int total = (cnt == 0) ? 1 : ((cnt < NSAMPLE) ? cnt : NSAMPLE);
    const int slot  = (lane < total) ? lane : 0;     // pad with first
    const int myidx = sidx[warp][slot];

    // --- grouped_xyz = xyz[idx] - new_xyz (re-load identical bits) ---------
    const float4 pg = __ldg(xp + myidx);
    const size_t cs    = (size_t)SS * NSAMPLE;
    const size_t obase = (((size_t)b * OUTCH) * SS + s) * NSAMPLE + lane;
    out[obase + 0 * cs] = pg.x - qx;
    out[obase + 1 * cs] = pg.y - qy;
    out[obase + 2 * cs] = pg.z - qz;

    // --- grouped_features: wavefront-optimal cooperative gather -------------
    const float* fT = g_featT + (size_t)b * NPTS * CC;
    float*       tw = tile[warp];

    const int csub = lane >> 3;       // store: channel sub-id (0..3)
    const int k4   = (lane & 7) * 4;  // store: first of 4 samples

#pragma unroll
    for (int h = 0; h < 2; h++) {     // two 32-channel halves
        // 32 coalesced 128B half-row loads (1 wavefront each), MLP=8
#pragma unroll
        for (int m0 = 0; m0 < NSAMPLE; m0 += 8) {
            float v[8];
#pragma unroll
            for (int mm = 0; mm < 8; mm++) {
                const int im = __shfl_sync(0xffffffffu, myidx, m0 + mm);
                v[mm] = __ldg(fT + (size_t)im * CC + h * 32 + lane);
            }
#pragma unroll
            for (int mm = 0; mm < 8; mm++)
                tw[(m0 + mm) * 33 + lane] = v[mm];
        }
        __syncwarp();
        // 8 STG.128: each instr covers 4 channels x 8 sample-quads.
        // LDS banks: (k4+j)*33 + c == k4+j+c (mod 32) -> conflict-free
#pragma unroll
        for (int cc = 0; cc < 8; cc++) {
            const int c = cc * 4 + csub;          // channel within half
            float4 o;
            o.x = tw[(k4 + 0) * 33 + c];
            o.y = tw[(k4 + 1) * 33 + c];
            o.z = tw[(k4 + 2) * 33 + c];
            o.w = tw[(k4 + 3) * 33 + c];
            float* dst = out + (((size_t)b * OUTCH + 3 + h * 32 + c) * SS + s)
                             * NSAMPLE + k4;
            *(float4*)dst = o;
        }
        __syncwarp();
    }
}

extern "C" void kernel_launch(void* const* d_in, const int* in_sizes, int n_in,
                              void* d_out, int out_size) {
    const float* xyz      = (const float*)d_in[0];   // [4, 8192, 3]
    const float* new_xyz  = (const float*)d_in[1];   // [4, 2048, 3]
    const float* features = (const float*)d_in[2];   // [4, 64, 8192]
    float* out = (float*)d_out;                      // [4, 67, 2048, 32]

    dim3 tb(8, 32);
    dim3 tg(NPTS / 128, CC / 32 + 1, BB);            // (64, 3, 4)
    transpose_kernel<<<tg, tb>>>(features, xyz);

    qg_kernel<<<(BB * SS) / WPB, 32 * WPB>>>(new_xyz, out);  // 4096 x 64
}

// round 17
// speedup vs baseline: 1.0353x; 1.0353x over previous
#include <cuda_runtime.h>
#include <cuda_bf16.h>

// Problem constants (fixed shapes from setup_inputs)
#define BB      4
#define NPTS    8192
#define SS      2048
#define CC      64
#define NSAMPLE 32
#define R2      0.04f     // 0.2^2
#define OUTCH   (3 + CC)  // 67

#define WPB     2         // warps per block (qg)
#define TSTRIDE 132       // transpose smem row stride (floats) — mult of 4

// Scratch: transposed features [B,N,C] (8MB); xyz+p2 AoS [B,N] float4 (512KB)
__device__ float  g_featT[(size_t)BB * NPTS * CC];
__device__ float4 g_xyzP4[(size_t)BB * NPTS];

// ---------------------------------------------------------------------------
// Kernel 1: transpose features [B,C,N] -> [B,N,C], fully vectorized
// (round-13 version, validated). Last y-slice packs xyz into float4
// (x, y, z, p2), p2 in EXACT reference rounding.
// ---------------------------------------------------------------------------
__global__ __launch_bounds__(256) void transpose_kernel(
    const float* __restrict__ feat,
    const float* __restrict__ xyz)
{
    const int b = blockIdx.z;

    if (blockIdx.y == CC / 32) {
        const int t = threadIdx.y * 8 + threadIdx.x;
        if (t < 128) {
            const int n = blockIdx.x * 128 + t;
            const float x = __ldg(xyz + ((size_t)b * NPTS + n) * 3 + 0);
            const float y = __ldg(xyz + ((size_t)b * NPTS + n) * 3 + 1);
            const float z = __ldg(xyz + ((size_t)b * NPTS + n) * 3 + 2);
            const float p2 = __fadd_rn(__fadd_rn(__fmul_rn(x, x),
                                                 __fmul_rn(y, y)),
                                       __fmul_rn(z, z));
            g_xyzP4[(size_t)b * NPTS + n] = make_float4(x, y, z, p2);
        }
        return;
    }

    __shared__ float tile[32 * TSTRIDE];

    const int n0 = blockIdx.x * 128;
    const int c0 = blockIdx.y * 32;
    const int tx = threadIdx.x;            // 0..7
    const int ty = threadIdx.y;            // 0..31

    const float* fb = feat + ((size_t)b * CC + c0 + ty) * NPTS + n0;
#pragma unroll
    for (int i = 0; i < 4; i++) {
        const float4 v = __ldg((const float4*)(fb + i * 32) + tx);
        *(float4*)&tile[ty * TSTRIDE + i * 32 + 4 * tx] = v;
    }
    __syncthreads();

    float* fT = g_featT + (size_t)b * NPTS * CC;
#pragma unroll
    for (int i = 0; i < 4; i++) {
        const int n = i * 32 + ty;
        float4 o;
        o.x = tile[(4 * tx + 0) * TSTRIDE + n];
        o.y = tile[(4 * tx + 1) * TSTRIDE + n];
        o.z = tile[(4 * tx + 2) * TSTRIDE + n];
        o.w = tile[(4 * tx + 3) * TSTRIDE + n];
        *(float4*)(fT + (size_t)(n0 + n) * CC + c0 + 4 * tx) = o;
    }
}

// ---------------------------------------------------------------------------
// Kernel 2: fused ball query + group (round-14 champion; launch_bounds(64,16)
// to cap regs at 64 and gain one extra resident block/SM).
// Scan: float4 (x,y,z,p2), ping-pong prefetch, skip-empty chunks, per-chunk
// break. Gather: wavefront-optimal cooperative pattern (validated).
// ---------------------------------------------------------------------------
__global__ __launch_bounds__(64, 16) void qg_kernel(
    const float* __restrict__ new_xyz,  // [B, S, 3]
    float* __restrict__ out)            // [B, 67, S, 32]
{
    __shared__ int   sidx[WPB][NSAMPLE];
    __shared__ float tile[WPB][NSAMPLE * 33];

    const int warp = threadIdx.x >> 5;
    const int lane = threadIdx.x & 31;
    const int w    = blockIdx.x * WPB + warp;  // query id in [0, B*S)
    const int b    = w / SS;
    const int s    = w % SS;

    const float* qptr = new_xyz + ((size_t)b * SS + s) * 3;
    const float qx = qptr[0], qy = qptr[1], qz = qptr[2];
    // Reference arithmetic EXACTLY (plain rn ops, no contraction):
    const float q2 = __fadd_rn(__fadd_rn(__fmul_rn(qx, qx), __fmul_rn(qy, qy)),
                               __fmul_rn(qz, qz));

    const float4* xp = g_xyzP4 + (size_t)b * NPTS;
    const unsigned lmask = (1u << lane) - 1u;

    int cnt = 0;

    // Evaluate one 128-point chunk held in p4[4]; update cnt/sidx.
    auto process = [&](const float4* p4, int base) {
        bool in[4];
#pragma unroll
        for (int r = 0; r < 4; r++) {
            const float4 p = p4[r];
            const float qpd = __fadd_rn(__fadd_rn(__fmul_rn(qx, p.x),
                                                  __fmul_rn(qy, p.y)),
                                        __fmul_rn(qz, p.z));
            const float d2  = __fadd_rn(__fadd_rn(q2, p.w),
                                        __fmul_rn(-2.0f, qpd));
            in[r] = d2 < R2;
        }
        unsigned m[4];
#pragma unroll
        for (int r = 0; r < 4; r++) m[r] = __ballot_sync(0xffffffffu, in[r]);

        // Skip all bookkeeping when the chunk has no hits (common on tails)
        if ((m[0] | m[1] | m[2] | m[3]) != 0u) {
            int pre[4];
            pre[0] = cnt;
            pre[1] = pre[0] + __popc(m[0]);
            pre[2] = pre[1] + __popc(m[1]);
            pre[3] = pre[2] + __popc(m[2]);
            const int newcnt = pre[3] + __popc(m[3]);
#pragma unroll
            for (int r = 0; r < 4; r++) {
                if (in[r]) {
                    const int pos = pre[r] + __popc(m[r] & lmask);
                    if (pos < NSAMPLE) sidx[warp][pos] = base + 32 * r + lane;
                }
            }
            cnt = newcnt;
        }
    };

    // Ping-pong scan: process A while prefetching B, and vice versa.
    {
        float4 A[4], B[4];
#pragma unroll
        for (int r = 0; r < 4; r++) A[r] = __ldg(xp + 32 * r + lane);

        int base = 0;
        for (;;) {
            if (base + 128 < NPTS) {
#pragma unroll
                for (int r = 0; r < 4; r++)
                    B[r] = __ldg(xp + base + 128 + 32 * r + lane);
            }
            process(A, base);
            base += 128;
            if (cnt >= NSAMPLE || base >= NPTS) break;

            if (base + 128 < NPTS) {
#pragma unroll
                for (int r = 0; r < 4; r++)
                    A[r] = __ldg(xp + base + 128 + 32 * r + lane);
            }
            process(B, base);
            base += 128;
            if (cnt >= NSAMPLE || base >= NPTS) break;
        }
    }

    // Empty-ball fallback: slot 0 = point 0 (matches reference idx=0)
    if (cnt == 0 && lane == 0) sidx[warp][0] = 0;
    __syncwarp();

    const int total = (cnt == 0) ? 1 : ((cnt < NSAMPLE) ? cnt : NSAMPLE);
    const int slot  = (lane < total) ? lane : 0;     // pad with first
    const int myidx = sidx[warp][slot];

    // --- grouped_xyz = xyz[idx] - new_xyz (re-load identical bits) ---------
    const float4 pg = __ldg(xp + myidx);
    const size_t cs    = (size_t)SS * NSAMPLE;
    const size_t obase = (((size_t)b * OUTCH) * SS + s) * NSAMPLE + lane;
    out[obase + 0 * cs] = pg.x - qx;
    out[obase + 1 * cs] = pg.y - qy;
    out[obase + 2 * cs] = pg.z - qz;

    // --- grouped_features: wavefront-optimal cooperative gather -------------
    const float* fT = g_featT + (size_t)b * NPTS * CC;
    float*       tw = tile[warp];

    const int csub = lane >> 3;       // store: channel sub-id (0..3)
    const int k4   = (lane & 7) * 4;  // store: first of 4 samples

#pragma unroll
    for (int h = 0; h < 2; h++) {     // two 32-channel halves
        // 32 coalesced 128B half-row loads (1 wavefront each), MLP=8
#pragma unroll
        for (int m0 = 0; m0 < NSAMPLE; m0 += 8) {
            float v[8];
#pragma unroll
            for (int mm = 0; mm < 8; mm++) {
                const int im = __shfl_sync(0xffffffffu, myidx, m0 + mm);
                v[mm] = __ldg(fT + (size_t)im * CC + h * 32 + lane);
            }
#pragma unroll
            for (int mm = 0; mm < 8; mm++)
                tw[(m0 + mm) * 33 + lane] = v[mm];
        }
        __syncwarp();
        // 8 STG.128: each instr covers 4 channels x 8 sample-quads.
        // LDS banks: (k4+j)*33 + c == k4+j+c (mod 32) -> conflict-free
#pragma unroll
        for (int cc = 0; cc < 8; cc++) {
            const int c = cc * 4 + csub;          // channel within half
            float4 o;
            o.x = tw[(k4 + 0) * 33 + c];
            o.y = tw[(k4 + 1) * 33 + c];
            o.z = tw[(k4 + 2) * 33 + c];
            o.w = tw[(k4 + 3) * 33 + c];
            float* dst = out + (((size_t)b * OUTCH + 3 + h * 32 + c) * SS + s)
                             * NSAMPLE + k4;
            *(float4*)dst = o;
        }
        __syncwarp();
    }
}

extern "C" void kernel_launch(void* const* d_in, const int* in_sizes, int n_in,
                              void* d_out, int out_size) {
    const float* xyz      = (const float*)d_in[0];   // [4, 8192, 3]
    const float* new_xyz  = (const float*)d_in[1];   // [4, 2048, 3]
    const float* features = (const float*)d_in[2];   // [4, 64, 8192]
    float* out = (float*)d_out;                      // [4, 67, 2048, 32]

    dim3 tb(8, 32);
    dim3 tg(NPTS / 128, CC / 32 + 1, BB);            // (64, 3, 4)
    transpose_kernel<<<tg, tb>>>(features, xyz);

    qg_kernel<<<(BB * SS) / WPB, 32 * WPB>>>(new_xyz, out);  // 4096 x 64
}